// round 1
// baseline (speedup 1.0000x reference)
#include <cuda_runtime.h>
#include <math.h>
#include <stdint.h>

// Problem dimensions (fixed by the reference).
#define B_  2
#define S_  2048
#define D_  1024
#define H_  16
#define DK_ 64
#define M_  (B_ * S_)

// Scratch (device globals: allowed; runtime allocation is not).
__device__ float g_q[(size_t)B_ * H_ * S_ * DK_];     // (B,H,S,DK)
__device__ float g_k[(size_t)B_ * H_ * S_ * DK_];
__device__ float g_v[(size_t)B_ * H_ * S_ * DK_];
__device__ float g_attn[(size_t)B_ * S_ * D_];        // (B,S,D)

// ---------------------------------------------------------------------------
// GEMM core: C[m,e] = sum_d A[m,d] * W[e,d]   (both operands d-contiguous)
// BM=64, BN=128, BK=16, 256 threads, 4x8 per-thread tile.
// Thread (ty,tx): rows m0+ty*4+i (i<4), cols e0+tx+16*j (j<8).
// ---------------------------------------------------------------------------
__device__ __forceinline__ void gemm_core(const float* __restrict__ A,
                                          const float* __restrict__ W,
                                          int m0, int e0, int tid,
                                          float (&c)[4][8],
                                          float (*As)[17], float (*Ws)[17])
{
    const int tx = tid & 15;
    const int ty = tid >> 4;

    for (int k0 = 0; k0 < D_; k0 += 16) {
        // Load A tile 64x16 (one float4 per thread, fully coalesced)
        {
            const int row = tid >> 2;
            const int col = (tid & 3) << 2;
            const float4 a4 = *reinterpret_cast<const float4*>(
                A + (size_t)(m0 + row) * D_ + k0 + col);
            As[row][col + 0] = a4.x; As[row][col + 1] = a4.y;
            As[row][col + 2] = a4.z; As[row][col + 3] = a4.w;
        }
        // Load W tile 128x16 (two float4 per thread)
        #pragma unroll
        for (int t = 0; t < 2; ++t) {
            const int idx = tid + t * 256;
            const int row = idx >> 2;
            const int col = (idx & 3) << 2;
            const float4 w4 = *reinterpret_cast<const float4*>(
                W + (size_t)(e0 + row) * D_ + k0 + col);
            Ws[row][col + 0] = w4.x; Ws[row][col + 1] = w4.y;
            Ws[row][col + 2] = w4.z; Ws[row][col + 3] = w4.w;
        }
        __syncthreads();

        #pragma unroll
        for (int d = 0; d < 16; ++d) {
            float a[4], b[8];
            #pragma unroll
            for (int i = 0; i < 4; ++i) a[i] = As[ty * 4 + i][d];     // broadcast
            #pragma unroll
            for (int j = 0; j < 8; ++j) b[j] = Ws[tx + 16 * j][d];    // conflict-free (pitch 17)
            #pragma unroll
            for (int i = 0; i < 4; ++i)
                #pragma unroll
                for (int j = 0; j < 8; ++j)
                    c[i][j] = fmaf(a[i], b[j], c[i][j]);
        }
        __syncthreads();
    }
}

// ---------------------------------------------------------------------------
// QKV projection: y = x @ W^T + bias, scattered into (B,H,S,DK) layout.
// grid = (M/64, D/128, 3), z selects Q/K/V.
// ---------------------------------------------------------------------------
__global__ __launch_bounds__(256) void proj_qkv_kernel(
    const float* __restrict__ x,
    const float* __restrict__ wq, const float* __restrict__ bq,
    const float* __restrict__ wk, const float* __restrict__ bk,
    const float* __restrict__ wv, const float* __restrict__ bv)
{
    __shared__ float As[64][17];
    __shared__ float Ws[128][17];

    const int mode = blockIdx.z;
    const float* w   = (mode == 0) ? wq : (mode == 1) ? wk : wv;
    const float* bia = (mode == 0) ? bq : (mode == 1) ? bk : bv;
    float* out       = (mode == 0) ? g_q : (mode == 1) ? g_k : g_v;

    const int tid = threadIdx.x;
    const int tx = tid & 15, ty = tid >> 4;
    const int m0 = blockIdx.x * 64;
    const int e0 = blockIdx.y * 128;

    float c[4][8];
    #pragma unroll
    for (int i = 0; i < 4; ++i)
        #pragma unroll
        for (int j = 0; j < 8; ++j) c[i][j] = 0.f;

    gemm_core(x, w, m0, e0, tid, c, As, Ws);

    #pragma unroll
    for (int j = 0; j < 8; ++j) {
        const int e  = e0 + tx + 16 * j;
        const float bb = bia[e];
        const int h  = e >> 6;
        const int dk = e & (DK_ - 1);
        #pragma unroll
        for (int i = 0; i < 4; ++i) {
            const int m = m0 + ty * 4 + i;
            const int b = m >> 11;          // m / S_
            const int s = m & (S_ - 1);
            out[((size_t)(b * H_ + h) * S_ + s) * DK_ + dk] = c[i][j] + bb;
        }
    }
}

// ---------------------------------------------------------------------------
// Output projection: out = attn @ wo^T + bo, plain (B,S,D) layout.
// ---------------------------------------------------------------------------
__global__ __launch_bounds__(256) void proj_out_kernel(
    const float* __restrict__ wo, const float* __restrict__ bo,
    float* __restrict__ out)
{
    __shared__ float As[64][17];
    __shared__ float Ws[128][17];

    const int tid = threadIdx.x;
    const int tx = tid & 15, ty = tid >> 4;
    const int m0 = blockIdx.x * 64;
    const int e0 = blockIdx.y * 128;

    float c[4][8];
    #pragma unroll
    for (int i = 0; i < 4; ++i)
        #pragma unroll
        for (int j = 0; j < 8; ++j) c[i][j] = 0.f;

    gemm_core(g_attn, wo, m0, e0, tid, c, As, Ws);

    #pragma unroll
    for (int j = 0; j < 8; ++j) {
        const int e = e0 + tx + 16 * j;
        const float bb = bo[e];
        #pragma unroll
        for (int i = 0; i < 4; ++i) {
            const int m = m0 + ty * 4 + i;
            out[(size_t)m * D_ + e] = c[i][j] + bb;
        }
    }
}

// ---------------------------------------------------------------------------
// Flash attention: one CTA = 128 query rows of one (b,h), loop over 64-key
// tiles with online softmax. 256 threads; thread (ty,tx) owns rows ty*8+i,
// key/dk columns tx+16*j.
// ---------------------------------------------------------------------------
#define FLASH_SMEM ((128*65 + 64*65 + 64*64 + 128*65) * 4)   // 99584 bytes

__global__ __launch_bounds__(256) void flash_kernel()
{
    extern __shared__ float sm[];
    float (*Qs)[65] = reinterpret_cast<float(*)[65]>(sm);                       // 128 x 64 (pitch 65)
    float (*Ks)[65] = reinterpret_cast<float(*)[65]>(sm + 128 * 65);            //  64 x 64 (pitch 65)
    float (*Vs)[64] = reinterpret_cast<float(*)[64]>(sm + 128 * 65 + 64 * 65);  //  64 x 64 (no pad)
    float (*Ps)[65] = reinterpret_cast<float(*)[65]>(sm + 128 * 65 + 64 * 65 + 64 * 64); // 128 x 64

    const int tid = threadIdx.x;
    const int tx = tid & 15, ty = tid >> 4;
    const int bh = blockIdx.y;
    const int q0 = blockIdx.x * 128;

    const float* qp = g_q + (size_t)bh * S_ * DK_;
    const float* kp = g_k + (size_t)bh * S_ * DK_;
    const float* vp = g_v + (size_t)bh * S_ * DK_;

    // Load Q tile with 1/sqrt(DK) folded in.
    const float scale = 0.125f;
    #pragma unroll
    for (int t = 0; t < 8; ++t) {
        const int idx = tid + t * 256;           // float4 index within 128x64 tile
        const int row = idx >> 4;
        const int col = (idx & 15) << 2;
        const float4 q4 = *reinterpret_cast<const float4*>(
            qp + (size_t)(q0 + row) * DK_ + col);
        Qs[row][col + 0] = q4.x * scale; Qs[row][col + 1] = q4.y * scale;
        Qs[row][col + 2] = q4.z * scale; Qs[row][col + 3] = q4.w * scale;
    }

    float m_i[8], l_i[8], o[8][4];
    #pragma unroll
    for (int i = 0; i < 8; ++i) {
        m_i[i] = -INFINITY; l_i[i] = 0.f;
        #pragma unroll
        for (int j = 0; j < 4; ++j) o[i][j] = 0.f;
    }

    for (int kt = 0; kt < S_ / 64; ++kt) {
        __syncthreads();   // previous PV reads done; Q visible on first iter
        const float* kb = kp + (size_t)kt * 64 * DK_;
        const float* vb = vp + (size_t)kt * 64 * DK_;
        #pragma unroll
        for (int t = 0; t < 4; ++t) {
            const int idx = tid + t * 256;
            const int row = idx >> 4;
            const int col = (idx & 15) << 2;
            const float4 k4 = *reinterpret_cast<const float4*>(kb + (size_t)row * DK_ + col);
            Ks[row][col + 0] = k4.x; Ks[row][col + 1] = k4.y;
            Ks[row][col + 2] = k4.z; Ks[row][col + 3] = k4.w;
            const float4 v4 = *reinterpret_cast<const float4*>(vb + (size_t)row * DK_ + col);
            Vs[row][col + 0] = v4.x; Vs[row][col + 1] = v4.y;
            Vs[row][col + 2] = v4.z; Vs[row][col + 3] = v4.w;
        }
        __syncthreads();

        // Scores: S = (Q*scale) K^T  -- 8x4 per thread
        float s[8][4];
        #pragma unroll
        for (int i = 0; i < 8; ++i)
            #pragma unroll
            for (int j = 0; j < 4; ++j) s[i][j] = 0.f;

        #pragma unroll 8
        for (int d = 0; d < DK_; ++d) {
            float qf[8], kf[4];
            #pragma unroll
            for (int i = 0; i < 8; ++i) qf[i] = Qs[ty * 8 + i][d];   // broadcast
            #pragma unroll
            for (int j = 0; j < 4; ++j) kf[j] = Ks[tx + 16 * j][d];  // conflict-free
            #pragma unroll
            for (int i = 0; i < 8; ++i)
                #pragma unroll
                for (int j = 0; j < 4; ++j)
                    s[i][j] = fmaf(qf[i], kf[j], s[i][j]);
        }

        // Online softmax (row reductions across the 16 tx lanes)
        #pragma unroll
        for (int i = 0; i < 8; ++i) {
            float mx = fmaxf(fmaxf(s[i][0], s[i][1]), fmaxf(s[i][2], s[i][3]));
            mx = fmaxf(mx, __shfl_xor_sync(0xffffffffu, mx, 8));
            mx = fmaxf(mx, __shfl_xor_sync(0xffffffffu, mx, 4));
            mx = fmaxf(mx, __shfl_xor_sync(0xffffffffu, mx, 2));
            mx = fmaxf(mx, __shfl_xor_sync(0xffffffffu, mx, 1));
            const float mnew  = fmaxf(m_i[i], mx);
            const float alpha = __expf(m_i[i] - mnew);   // first tile: exp(-inf)=0
            m_i[i] = mnew;
            float rs = 0.f;
            #pragma unroll
            for (int j = 0; j < 4; ++j) {
                s[i][j] = __expf(s[i][j] - mnew);
                rs += s[i][j];
            }
            rs += __shfl_xor_sync(0xffffffffu, rs, 8);
            rs += __shfl_xor_sync(0xffffffffu, rs, 4);
            rs += __shfl_xor_sync(0xffffffffu, rs, 2);
            rs += __shfl_xor_sync(0xffffffffu, rs, 1);
            l_i[i] = l_i[i] * alpha + rs;
            #pragma unroll
            for (int j = 0; j < 4; ++j) o[i][j] *= alpha;
        }

        // Stage P to smem for the PV GEMM
        #pragma unroll
        for (int i = 0; i < 8; ++i)
            #pragma unroll
            for (int j = 0; j < 4; ++j)
                Ps[ty * 8 + i][tx + 16 * j] = s[i][j];
        __syncthreads();

        // O += P @ V
        #pragma unroll 8
        for (int k = 0; k < 64; ++k) {
            float pf[8], vf[4];
            #pragma unroll
            for (int i = 0; i < 8; ++i) pf[i] = Ps[ty * 8 + i][k];   // broadcast
            #pragma unroll
            for (int j = 0; j < 4; ++j) vf[j] = Vs[k][tx + 16 * j];  // conflict-free
            #pragma unroll
            for (int i = 0; i < 8; ++i)
                #pragma unroll
                for (int j = 0; j < 4; ++j)
                    o[i][j] = fmaf(pf[i], vf[j], o[i][j]);
        }
    }

    // Epilogue: normalize and scatter back to (B,S,D)
    const int b = bh >> 4;          // bh / H_
    const int h = bh & (H_ - 1);
    #pragma unroll
    for (int i = 0; i < 8; ++i) {
        const float inv = 1.f / l_i[i];
        const int r = q0 + ty * 8 + i;
        #pragma unroll
        for (int j = 0; j < 4; ++j)
            g_attn[(size_t)(b * S_ + r) * D_ + h * DK_ + tx + 16 * j] = o[i][j] * inv;
    }
}

// ---------------------------------------------------------------------------
// Launch
// ---------------------------------------------------------------------------
extern "C" void kernel_launch(void* const* d_in, const int* in_sizes, int n_in,
                              void* d_out, int out_size)
{
    const float* x  = (const float*)d_in[0];
    const float* wq = (const float*)d_in[1];
    const float* bq = (const float*)d_in[2];
    const float* wk = (const float*)d_in[3];
    const float* bk = (const float*)d_in[4];
    const float* wv = (const float*)d_in[5];
    const float* bv = (const float*)d_in[6];
    const float* wo = (const float*)d_in[7];
    const float* bo = (const float*)d_in[8];
    float* out = (float*)d_out;

    cudaFuncSetAttribute(flash_kernel,
                         cudaFuncAttributeMaxDynamicSharedMemorySize, FLASH_SMEM);

    proj_qkv_kernel<<<dim3(M_ / 64, D_ / 128, 3), 256>>>(x, wq, bq, wk, bk, wv, bv);
    flash_kernel<<<dim3(S_ / 128, B_ * H_), 256, FLASH_SMEM>>>();
    proj_out_kernel<<<dim3(M_ / 64, D_ / 128), 256>>>(wo, bo, out);
}

// round 3
// speedup vs baseline: 1.6540x; 1.6540x over previous
#include <cuda_runtime.h>
#include <math.h>
#include <stdint.h>

// Problem dimensions (fixed by the reference).
#define B_  2
#define S_  2048
#define D_  1024
#define H_  16
#define DK_ 64
#define M_  (B_ * S_)

#define NCHUNK (D_ / 32)          // 32 K-chunks of 32 floats

// Scratch (device globals: allowed; runtime allocation is not).
static __device__ float g_xr [(size_t)M_ * D_];                    // rna(x)
static __device__ float g_wr [(size_t)4 * D_ * D_];                // rna(wq,wk,wv,wo)
static __device__ float g_qkv[(size_t)3 * B_ * H_ * S_ * DK_];     // q,k,v (B,H,S,DK)
static __device__ float g_attn[(size_t)M_ * D_];                   // rna(attn out) (B,S,D)

// ---------------------------------------------------------------------------
// Helpers
// ---------------------------------------------------------------------------
__device__ __forceinline__ uint32_t smem_u32(const void* p) {
    uint32_t a;
    asm("{ .reg .u64 t; cvta.to.shared.u64 t, %1; cvt.u32.u64 %0, t; }" : "=r"(a) : "l"(p));
    return a;
}

__device__ __forceinline__ float rna_tf32(float f) {
    uint32_t u;
    asm("cvt.rna.tf32.f32 %0, %1;" : "=r"(u) : "f"(f));
    return __uint_as_float(u);
}

#define CP16(dst, src) \
    asm volatile("cp.async.cg.shared.global [%0], [%1], 16;" :: "r"(dst), "l"(src) : "memory")
#define CP_COMMIT()  asm volatile("cp.async.commit_group;" ::: "memory")
#define CP_WAIT(n)   asm volatile("cp.async.wait_group %0;" :: "n"(n) : "memory")

// m16n8k8 tf32 MMA: D += A * B  (A row-major 16x8, B col-major 8x8)
#define MMA_TF32(d, a, b) \
    asm volatile( \
        "mma.sync.aligned.m16n8k8.row.col.f32.tf32.tf32.f32 " \
        "{%0,%1,%2,%3}, {%4,%5,%6,%7}, {%8,%9}, {%0,%1,%2,%3};" \
        : "+f"((d)[0]), "+f"((d)[1]), "+f"((d)[2]), "+f"((d)[3]) \
        : "r"((a)[0]), "r"((a)[1]), "r"((a)[2]), "r"((a)[3]), \
          "r"((b)[0]), "r"((b)[1]))

// ---------------------------------------------------------------------------
// GEMM body: C[128x128] = A[128xD] * W[128xD]^T  (both row-major, d-contig)
// 256 threads = 8 warps; warp (wid>>1 = m-quad, wid&1 = n-half) owns 32x64.
// Smem pitch 36 floats => fragment LDS bank = (4r + c) mod 32, conflict-free.
// 2-stage cp.async pipeline, K=32 per chunk.
// ---------------------------------------------------------------------------
#define PITCH 36
#define STAGE_F (2 * 128 * PITCH)          // floats per stage (A + W)
#define GEMM_SMEM (2 * STAGE_F * 4)        // 73728 bytes

__device__ __forceinline__ void issue_chunk(const float* __restrict__ Ag,
                                            const float* __restrict__ Wg,
                                            float* sm, int stage, int c, int tid)
{
    float* As = sm + stage * STAGE_F;
    float* Ws = As + 128 * PITCH;
    const uint32_t aB = smem_u32(As), wB = smem_u32(Ws);
    const int kb = c * 32;
    #pragma unroll
    for (int t = 0; t < 4; ++t) {
        const int idx = tid + (t << 8);        // 0..1023
        const int row = idx >> 3;
        const int col = (idx & 7) << 2;
        const uint32_t so = (uint32_t)(row * PITCH + col) * 4u;
        CP16(aB + so, Ag + (size_t)row * D_ + kb + col);
        CP16(wB + so, Wg + (size_t)row * D_ + kb + col);
    }
    CP_COMMIT();
}

__device__ __forceinline__ void compute_chunk(const float* __restrict__ As,
                                              const float* __restrict__ Ws,
                                              float (&acc)[2][8][4],
                                              int g, int tg, int m_w0, int n_w0)
{
    #pragma unroll
    for (int k8 = 0; k8 < 4; ++k8) {
        const int kb = k8 * 8;
        uint32_t a[2][4], b[8][2];
        #pragma unroll
        for (int mi = 0; mi < 2; ++mi) {
            const float* r0 = As + (size_t)(m_w0 + mi * 16 + g) * PITCH;
            const float* r1 = r0 + 8 * PITCH;
            a[mi][0] = __float_as_uint(r0[kb + tg]);
            a[mi][1] = __float_as_uint(r1[kb + tg]);
            a[mi][2] = __float_as_uint(r0[kb + 4 + tg]);
            a[mi][3] = __float_as_uint(r1[kb + 4 + tg]);
        }
        #pragma unroll
        for (int nj = 0; nj < 8; ++nj) {
            const float* br = Ws + (size_t)(n_w0 + nj * 8 + g) * PITCH;
            b[nj][0] = __float_as_uint(br[kb + tg]);
            b[nj][1] = __float_as_uint(br[kb + 4 + tg]);
        }
        #pragma unroll
        for (int mi = 0; mi < 2; ++mi)
            #pragma unroll
            for (int nj = 0; nj < 8; ++nj)
                MMA_TF32(acc[mi][nj], a[mi], b[nj]);
    }
}

__device__ __forceinline__ void tc_gemm_body(const float* __restrict__ Ag,
                                             const float* __restrict__ Wg,
                                             float* sm, float (&acc)[2][8][4],
                                             int m_w0, int n_w0)
{
    const int tid = threadIdx.x;
    const int lane = tid & 31;
    const int g = lane >> 2, tg = lane & 3;

    issue_chunk(Ag, Wg, sm, 0, 0, tid);

    for (int c = 0; c < NCHUNK; ++c) {
        if (c + 1 < NCHUNK) {
            issue_chunk(Ag, Wg, sm, (c + 1) & 1, c + 1, tid);
            CP_WAIT(1);
        } else {
            CP_WAIT(0);
        }
        __syncthreads();
        const float* As = sm + (c & 1) * STAGE_F;
        compute_chunk(As, As + 128 * PITCH, acc, g, tg, m_w0, n_w0);
        __syncthreads();
    }
}

// ---------------------------------------------------------------------------
// Prep: round x + weights to tf32 (rna) copies.
// ---------------------------------------------------------------------------
__global__ __launch_bounds__(256) void prep_kernel(
    const float* __restrict__ x,
    const float* __restrict__ wq, const float* __restrict__ wk,
    const float* __restrict__ wv, const float* __restrict__ wo)
{
    const int r = blockIdx.y;
    const float* src = (r == 0) ? x : (r == 1) ? wq : (r == 2) ? wk : (r == 3) ? wv : wo;
    float* dst = (r == 0) ? g_xr : g_wr + (size_t)(r - 1) * D_ * D_;
    const size_t n = (r == 0) ? (size_t)M_ * D_ : (size_t)D_ * D_;
    const size_t i = ((size_t)blockIdx.x * 256 + threadIdx.x) * 4;
    if (i < n) {
        float4 v = *reinterpret_cast<const float4*>(src + i);
        v.x = rna_tf32(v.x); v.y = rna_tf32(v.y);
        v.z = rna_tf32(v.z); v.w = rna_tf32(v.w);
        *reinterpret_cast<float4*>(dst + i) = v;
    }
}

// ---------------------------------------------------------------------------
// QKV projection (tensor core): grid (32, 8, 3), 256 threads.
// ---------------------------------------------------------------------------
__global__ __launch_bounds__(256) void tc_gemm_qkv(
    const float* __restrict__ bq, const float* __restrict__ bk,
    const float* __restrict__ bv)
{
    extern __shared__ float sm[];
    const int z = blockIdx.z;
    const float* bias = (z == 0) ? bq : (z == 1) ? bk : bv;
    const float* W = g_wr + (size_t)z * D_ * D_;
    float* out = g_qkv + (size_t)z * ((size_t)B_ * H_ * S_ * DK_);

    const int m0 = blockIdx.x * 128;
    const int e0 = blockIdx.y * 128;
    const int tid = threadIdx.x, wid = tid >> 5, lane = tid & 31;
    const int m_w0 = (wid >> 1) * 32, n_w0 = (wid & 1) * 64;

    float acc[2][8][4];
    #pragma unroll
    for (int mi = 0; mi < 2; ++mi)
        #pragma unroll
        for (int nj = 0; nj < 8; ++nj)
            #pragma unroll
            for (int q = 0; q < 4; ++q) acc[mi][nj][q] = 0.f;

    tc_gemm_body(g_xr + (size_t)m0 * D_, W + (size_t)e0 * D_, sm, acc, m_w0, n_w0);

    const int g = lane >> 2, tg = lane & 3;
    #pragma unroll
    for (int mi = 0; mi < 2; ++mi) {
        #pragma unroll
        for (int half = 0; half < 2; ++half) {
            const int m = m0 + m_w0 + mi * 16 + g + half * 8;
            const int b = m >> 11;
            const int s = m & (S_ - 1);
            #pragma unroll
            for (int nj = 0; nj < 8; ++nj) {
                const int col = e0 + n_w0 + nj * 8 + 2 * tg;
                const int h = col >> 6, dk = col & (DK_ - 1);
                float2 v;
                v.x = acc[mi][nj][2 * half + 0] + bias[col];
                v.y = acc[mi][nj][2 * half + 1] + bias[col + 1];
                *reinterpret_cast<float2*>(
                    out + ((size_t)(b * H_ + h) * S_ + s) * DK_ + dk) = v;
            }
        }
    }
}

// ---------------------------------------------------------------------------
// Output projection (tensor core): grid (32, 8), 256 threads.
// ---------------------------------------------------------------------------
__global__ __launch_bounds__(256) void tc_gemm_out(
    const float* __restrict__ bo, float* __restrict__ out)
{
    extern __shared__ float sm[];
    const int m0 = blockIdx.x * 128;
    const int e0 = blockIdx.y * 128;
    const int tid = threadIdx.x, wid = tid >> 5, lane = tid & 31;
    const int m_w0 = (wid >> 1) * 32, n_w0 = (wid & 1) * 64;

    float acc[2][8][4];
    #pragma unroll
    for (int mi = 0; mi < 2; ++mi)
        #pragma unroll
        for (int nj = 0; nj < 8; ++nj)
            #pragma unroll
            for (int q = 0; q < 4; ++q) acc[mi][nj][q] = 0.f;

    tc_gemm_body(g_attn + (size_t)m0 * D_,
                 g_wr + (size_t)3 * D_ * D_ + (size_t)e0 * D_, sm, acc, m_w0, n_w0);

    const int g = lane >> 2, tg = lane & 3;
    #pragma unroll
    for (int mi = 0; mi < 2; ++mi) {
        #pragma unroll
        for (int half = 0; half < 2; ++half) {
            const int m = m0 + m_w0 + mi * 16 + g + half * 8;
            #pragma unroll
            for (int nj = 0; nj < 8; ++nj) {
                const int col = e0 + n_w0 + nj * 8 + 2 * tg;
                float2 v;
                v.x = acc[mi][nj][2 * half + 0] + bo[col];
                v.y = acc[mi][nj][2 * half + 1] + bo[col + 1];
                *reinterpret_cast<float2*>(out + (size_t)m * D_ + col) = v;
            }
        }
    }
}

// ---------------------------------------------------------------------------
// Flash attention (SIMT, unchanged; stores rna-rounded attn for the tf32 O-proj)
// ---------------------------------------------------------------------------
#define FLASH_SMEM ((128*65 + 64*65 + 64*64 + 128*65) * 4)   // 99584 bytes

__global__ __launch_bounds__(256) void flash_kernel()
{
    extern __shared__ float smf[];
    float (*Qs)[65] = reinterpret_cast<float(*)[65]>(smf);
    float (*Ks)[65] = reinterpret_cast<float(*)[65]>(smf + 128 * 65);
    float (*Vs)[64] = reinterpret_cast<float(*)[64]>(smf + 128 * 65 + 64 * 65);
    float (*Ps)[65] = reinterpret_cast<float(*)[65]>(smf + 128 * 65 + 64 * 65 + 64 * 64);

    const int tid = threadIdx.x;
    const int tx = tid & 15, ty = tid >> 4;
    const int bh = blockIdx.y;
    const int q0 = blockIdx.x * 128;

    const size_t qkv_sz = (size_t)B_ * H_ * S_ * DK_;
    const float* qp = g_qkv +              (size_t)bh * S_ * DK_;
    const float* kp = g_qkv + qkv_sz     + (size_t)bh * S_ * DK_;
    const float* vp = g_qkv + 2 * qkv_sz + (size_t)bh * S_ * DK_;

    const float scale = 0.125f;
    #pragma unroll
    for (int t = 0; t < 8; ++t) {
        const int idx = tid + t * 256;
        const int row = idx >> 4;
        const int col = (idx & 15) << 2;
        const float4 q4 = *reinterpret_cast<const float4*>(
            qp + (size_t)(q0 + row) * DK_ + col);
        Qs[row][col + 0] = q4.x * scale; Qs[row][col + 1] = q4.y * scale;
        Qs[row][col + 2] = q4.z * scale; Qs[row][col + 3] = q4.w * scale;
    }

    float m_i[8], l_i[8], o[8][4];
    #pragma unroll
    for (int i = 0; i < 8; ++i) {
        m_i[i] = -INFINITY; l_i[i] = 0.f;
        #pragma unroll
        for (int j = 0; j < 4; ++j) o[i][j] = 0.f;
    }

    for (int kt = 0; kt < S_ / 64; ++kt) {
        __syncthreads();
        const float* kb = kp + (size_t)kt * 64 * DK_;
        const float* vb = vp + (size_t)kt * 64 * DK_;
        #pragma unroll
        for (int t = 0; t < 4; ++t) {
            const int idx = tid + t * 256;
            const int row = idx >> 4;
            const int col = (idx & 15) << 2;
            const float4 k4 = *reinterpret_cast<const float4*>(kb + (size_t)row * DK_ + col);
            Ks[row][col + 0] = k4.x; Ks[row][col + 1] = k4.y;
            Ks[row][col + 2] = k4.z; Ks[row][col + 3] = k4.w;
            const float4 v4 = *reinterpret_cast<const float4*>(vb + (size_t)row * DK_ + col);
            Vs[row][col + 0] = v4.x; Vs[row][col + 1] = v4.y;
            Vs[row][col + 2] = v4.z; Vs[row][col + 3] = v4.w;
        }
        __syncthreads();

        float s[8][4];
        #pragma unroll
        for (int i = 0; i < 8; ++i)
            #pragma unroll
            for (int j = 0; j < 4; ++j) s[i][j] = 0.f;

        #pragma unroll 8
        for (int d = 0; d < DK_; ++d) {
            float qf[8], kf[4];
            #pragma unroll
            for (int i = 0; i < 8; ++i) qf[i] = Qs[ty * 8 + i][d];
            #pragma unroll
            for (int j = 0; j < 4; ++j) kf[j] = Ks[tx + 16 * j][d];
            #pragma unroll
            for (int i = 0; i < 8; ++i)
                #pragma unroll
                for (int j = 0; j < 4; ++j)
                    s[i][j] = fmaf(qf[i], kf[j], s[i][j]);
        }

        #pragma unroll
        for (int i = 0; i < 8; ++i) {
            float mx = fmaxf(fmaxf(s[i][0], s[i][1]), fmaxf(s[i][2], s[i][3]));
            mx = fmaxf(mx, __shfl_xor_sync(0xffffffffu, mx, 8));
            mx = fmaxf(mx, __shfl_xor_sync(0xffffffffu, mx, 4));
            mx = fmaxf(mx, __shfl_xor_sync(0xffffffffu, mx, 2));
            mx = fmaxf(mx, __shfl_xor_sync(0xffffffffu, mx, 1));
            const float mnew  = fmaxf(m_i[i], mx);
            const float alpha = __expf(m_i[i] - mnew);
            m_i[i] = mnew;
            float rs = 0.f;
            #pragma unroll
            for (int j = 0; j < 4; ++j) {
                s[i][j] = __expf(s[i][j] - mnew);
                rs += s[i][j];
            }
            rs += __shfl_xor_sync(0xffffffffu, rs, 8);
            rs += __shfl_xor_sync(0xffffffffu, rs, 4);
            rs += __shfl_xor_sync(0xffffffffu, rs, 2);
            rs += __shfl_xor_sync(0xffffffffu, rs, 1);
            l_i[i] = l_i[i] * alpha + rs;
            #pragma unroll
            for (int j = 0; j < 4; ++j) o[i][j] *= alpha;
        }

        #pragma unroll
        for (int i = 0; i < 8; ++i)
            #pragma unroll
            for (int j = 0; j < 4; ++j)
                Ps[ty * 8 + i][tx + 16 * j] = s[i][j];
        __syncthreads();

        #pragma unroll 8
        for (int k = 0; k < 64; ++k) {
            float pf[8], vf[4];
            #pragma unroll
            for (int i = 0; i < 8; ++i) pf[i] = Ps[ty * 8 + i][k];
            #pragma unroll
            for (int j = 0; j < 4; ++j) vf[j] = Vs[k][tx + 16 * j];
            #pragma unroll
            for (int i = 0; i < 8; ++i)
                #pragma unroll
                for (int j = 0; j < 4; ++j)
                    o[i][j] = fmaf(pf[i], vf[j], o[i][j]);
        }
    }

    const int b = bh >> 4;
    const int h = bh & (H_ - 1);
    #pragma unroll
    for (int i = 0; i < 8; ++i) {
        const float inv = 1.f / l_i[i];
        const int r = q0 + ty * 8 + i;
        #pragma unroll
        for (int j = 0; j < 4; ++j)
            g_attn[(size_t)(b * S_ + r) * D_ + h * DK_ + tx + 16 * j] =
                rna_tf32(o[i][j] * inv);
    }
}

// ---------------------------------------------------------------------------
// Launch
// ---------------------------------------------------------------------------
extern "C" void kernel_launch(void* const* d_in, const int* in_sizes, int n_in,
                              void* d_out, int out_size)
{
    const float* x  = (const float*)d_in[0];
    const float* wq = (const float*)d_in[1];
    const float* bq = (const float*)d_in[2];
    const float* wk = (const float*)d_in[3];
    const float* bk = (const float*)d_in[4];
    const float* wv = (const float*)d_in[5];
    const float* bv = (const float*)d_in[6];
    const float* wo = (const float*)d_in[7];
    const float* bo = (const float*)d_in[8];
    float* out = (float*)d_out;

    cudaFuncSetAttribute(flash_kernel,
                         cudaFuncAttributeMaxDynamicSharedMemorySize, FLASH_SMEM);
    cudaFuncSetAttribute(tc_gemm_qkv,
                         cudaFuncAttributeMaxDynamicSharedMemorySize, GEMM_SMEM);
    cudaFuncSetAttribute(tc_gemm_out,
                         cudaFuncAttributeMaxDynamicSharedMemorySize, GEMM_SMEM);

    prep_kernel<<<dim3((M_ * D_) / 1024, 5), 256>>>(x, wq, wk, wv, wo);
    tc_gemm_qkv<<<dim3(M_ / 128, D_ / 128, 3), 256, GEMM_SMEM>>>(bq, bk, bv);
    flash_kernel<<<dim3(S_ / 128, B_ * H_), 256, FLASH_SMEM>>>();
    tc_gemm_out<<<dim3(M_ / 128, D_ / 128), 256, GEMM_SMEM>>>(bo, out);
}

// round 4
// speedup vs baseline: 6.7371x; 4.0731x over previous
#include <cuda_runtime.h>
#include <cuda_fp16.h>
#include <math.h>
#include <stdint.h>

// Problem dimensions (fixed by the reference).
#define B_  2
#define S_  2048
#define D_  1024
#define H_  16
#define DK_ 64
#define M_  (B_ * S_)

// Scratch (device globals: allowed; runtime allocation is not).
static __device__ __half g_xh[(size_t)M_ * D_];              // f16(x)
static __device__ __half g_wh[(size_t)4 * D_ * D_];          // f16(wq,wk,wv,wo)
static __device__ __half g_qh[(size_t)B_ * H_ * S_ * DK_];   // q * 0.125*log2e (B,H,S,DK)
static __device__ __half g_kh[(size_t)B_ * H_ * S_ * DK_];   // k (B,H,S,DK)
static __device__ __half g_vt[(size_t)B_ * H_ * DK_ * S_];   // v TRANSPOSED (B,H,DK,S)
static __device__ __half g_ah[(size_t)M_ * D_];              // attn out f16 (B,S,D)

// ---------------------------------------------------------------------------
// Helpers
// ---------------------------------------------------------------------------
__device__ __forceinline__ uint32_t smem_u32(const void* p) {
    uint32_t a;
    asm("{ .reg .u64 t; cvta.to.shared.u64 t, %1; cvt.u32.u64 %0, t; }" : "=r"(a) : "l"(p));
    return a;
}

__device__ __forceinline__ float exp2a(float x) {
    float y;
    asm("ex2.approx.f32 %0, %1;" : "=f"(y) : "f"(x));
    return y;
}

// packs {lo, hi} into f16x2 (first asm source = high half)
__device__ __forceinline__ uint32_t packh2(float hi, float lo) {
    uint32_t r;
    asm("cvt.rn.f16x2.f32 %0, %1, %2;" : "=r"(r) : "f"(hi), "f"(lo));
    return r;
}

#define CP16(dst, src) \
    asm volatile("cp.async.cg.shared.global [%0], [%1], 16;" :: "r"(dst), "l"(src) : "memory")
#define CP_COMMIT()  asm volatile("cp.async.commit_group;" ::: "memory")
#define CP_WAIT(n)   asm volatile("cp.async.wait_group %0;" :: "n"(n) : "memory")

// m16n8k16 f16 MMA, f32 accumulate: D += A(16x16 row) * B(16x8 col)
#define MMA_F16(d, a, b0, b1) \
    asm volatile( \
        "mma.sync.aligned.m16n8k16.row.col.f32.f16.f16.f32 " \
        "{%0,%1,%2,%3}, {%4,%5,%6,%7}, {%8,%9}, {%0,%1,%2,%3};" \
        : "+f"((d)[0]), "+f"((d)[1]), "+f"((d)[2]), "+f"((d)[3]) \
        : "r"((a)[0]), "r"((a)[1]), "r"((a)[2]), "r"((a)[3]), \
          "r"(b0), "r"(b1))

// ---------------------------------------------------------------------------
// f16 GEMM body: C[128x128] = A[128xD] * W[128xD]^T (f16 in, f32 acc)
// 256 threads / 8 warps; warp tile 32m x 64n. Smem rows of 32 u32 (64 f16),
// pitch 36 u32 -> every fragment LDS hits bank 4g+tg = lane (conflict-free).
// 2-stage cp.async, K-chunk = 64 f16.
// ---------------------------------------------------------------------------
#define PITCH 36
#define STAGE_U (2 * 128 * PITCH)          // u32 per stage (A + W)
#define GEMM_SMEM (2 * STAGE_U * 4)        // 73728 bytes

__device__ __forceinline__ void issue_chunk16(const __half* __restrict__ Ag,
                                              const __half* __restrict__ Wg,
                                              uint32_t* sm, int stage, int c, int tid)
{
    uint32_t* As = sm + stage * STAGE_U;
    uint32_t* Ws = As + 128 * PITCH;
    const char* Ab = (const char*)Ag + c * 128;   // 64 f16 = 128 B per chunk
    const char* Wb = (const char*)Wg + c * 128;
    #pragma unroll
    for (int t = 0; t < 8; ++t) {
        const int idx = tid + (t << 8);           // 0..2047
        const int sel = idx >> 10;                // 0 = A, 1 = W
        const int i2  = idx & 1023;
        const int row = i2 >> 3, ch = i2 & 7;
        const uint32_t dst = smem_u32((sel ? Ws : As) + row * PITCH + ch * 4);
        const char* src = (sel ? Wb : Ab) + (size_t)row * (D_ * 2) + ch * 16;
        CP16(dst, src);
    }
    CP_COMMIT();
}

__device__ __forceinline__ void compute_chunk16(const uint32_t* __restrict__ As,
                                                const uint32_t* __restrict__ Ws,
                                                float (&acc)[2][8][4],
                                                int g, int tg, int m_w0, int n_w0)
{
    #pragma unroll
    for (int s = 0; s < 4; ++s) {                 // 4 k16 steps per 64-f16 chunk
        uint32_t a[2][4];
        #pragma unroll
        for (int mi = 0; mi < 2; ++mi) {
            const uint32_t* r0 = As + (m_w0 + mi * 16 + g) * PITCH;
            const uint32_t* r1 = r0 + 8 * PITCH;
            a[mi][0] = r0[8 * s + tg];
            a[mi][1] = r1[8 * s + tg];
            a[mi][2] = r0[8 * s + tg + 4];
            a[mi][3] = r1[8 * s + tg + 4];
        }
        #pragma unroll
        for (int nj = 0; nj < 8; ++nj) {
            const uint32_t* br = Ws + (n_w0 + nj * 8 + g) * PITCH;
            const uint32_t b0 = br[8 * s + tg], b1 = br[8 * s + tg + 4];
            MMA_F16(acc[0][nj], a[0], b0, b1);
            MMA_F16(acc[1][nj], a[1], b0, b1);
        }
    }
}

__device__ __forceinline__ void gemm_body16(const __half* __restrict__ Ag,
                                            const __half* __restrict__ Wg,
                                            uint32_t* sm, float (&acc)[2][8][4],
                                            int m_w0, int n_w0, int tid, int g, int tg)
{
    issue_chunk16(Ag, Wg, sm, 0, 0, tid);
    for (int c = 0; c < 16; ++c) {
        if (c + 1 < 16) { issue_chunk16(Ag, Wg, sm, (c + 1) & 1, c + 1, tid); CP_WAIT(1); }
        else           { CP_WAIT(0); }
        __syncthreads();
        const uint32_t* As = sm + (c & 1) * STAGE_U;
        compute_chunk16(As, As + 128 * PITCH, acc, g, tg, m_w0, n_w0);
        __syncthreads();
    }
}

// ---------------------------------------------------------------------------
// Prep: convert x + weights to f16.
// ---------------------------------------------------------------------------
__global__ __launch_bounds__(256) void prep16(
    const float* __restrict__ x,
    const float* __restrict__ wq, const float* __restrict__ wk,
    const float* __restrict__ wv, const float* __restrict__ wo)
{
    const int r = blockIdx.y;
    const float* src = (r == 0) ? x : (r == 1) ? wq : (r == 2) ? wk : (r == 3) ? wv : wo;
    __half* dst = (r == 0) ? g_xh : g_wh + (size_t)(r - 1) * D_ * D_;
    const size_t n = (r == 0) ? (size_t)M_ * D_ : (size_t)D_ * D_;
    const size_t i = ((size_t)blockIdx.x * 256 + threadIdx.x) * 4;
    if (i < n) {
        const float4 v = *reinterpret_cast<const float4*>(src + i);
        uint2 o;
        o.x = packh2(v.y, v.x);
        o.y = packh2(v.w, v.z);
        *reinterpret_cast<uint2*>(dst + i) = o;
    }
}

// ---------------------------------------------------------------------------
// QKV projection: grid (32, 8, 3). Q gets 0.125*log2e folded in; V stored
// transposed (B,H,DK,S) for the flash B-operand.
// ---------------------------------------------------------------------------
__global__ __launch_bounds__(256) void proj_qkv16(
    const float* __restrict__ bq, const float* __restrict__ bk,
    const float* __restrict__ bv)
{
    extern __shared__ uint32_t sm[];
    const int z = blockIdx.z;
    const float* bias = (z == 0) ? bq : (z == 1) ? bk : bv;
    const __half* W = g_wh + (size_t)z * D_ * D_;

    const int m0 = blockIdx.x * 128, e0 = blockIdx.y * 128;
    const int tid = threadIdx.x, wid = tid >> 5, lane = tid & 31;
    const int g = lane >> 2, tg = lane & 3;
    const int m_w0 = (wid >> 1) * 32, n_w0 = (wid & 1) * 64;

    float acc[2][8][4];
    #pragma unroll
    for (int mi = 0; mi < 2; ++mi)
        #pragma unroll
        for (int nj = 0; nj < 8; ++nj)
            #pragma unroll
            for (int q = 0; q < 4; ++q) acc[mi][nj][q] = 0.f;

    gemm_body16(g_xh + (size_t)m0 * D_, W + (size_t)e0 * D_, sm, acc,
                m_w0, n_w0, tid, g, tg);

    #pragma unroll
    for (int mi = 0; mi < 2; ++mi) {
        #pragma unroll
        for (int hf = 0; hf < 2; ++hf) {
            const int m = m0 + m_w0 + mi * 16 + g + 8 * hf;
            const int b = m >> 11, s = m & (S_ - 1);
            #pragma unroll
            for (int nj = 0; nj < 8; ++nj) {
                const int e = e0 + n_w0 + nj * 8 + 2 * tg;
                float v0 = acc[mi][nj][2 * hf + 0] + bias[e];
                float v1 = acc[mi][nj][2 * hf + 1] + bias[e + 1];
                const int hh = e >> 6, dk = e & (DK_ - 1);
                const size_t bh = (size_t)(b * H_ + hh);
                if (z == 0) {
                    v0 *= 0.1803368801f;     // 0.125 * log2(e)
                    v1 *= 0.1803368801f;
                    ((uint32_t*)g_qh)[(bh * S_ + s) * 32 + (dk >> 1)] = packh2(v1, v0);
                } else if (z == 1) {
                    ((uint32_t*)g_kh)[(bh * S_ + s) * 32 + (dk >> 1)] = packh2(v1, v0);
                } else {
                    g_vt[(bh * DK_ + dk) * S_ + s]     = __float2half_rn(v0);
                    g_vt[(bh * DK_ + dk + 1) * S_ + s] = __float2half_rn(v1);
                }
            }
        }
    }
}

// ---------------------------------------------------------------------------
// Output projection: grid (32, 8), reads f16 attn, writes f32 out.
// ---------------------------------------------------------------------------
__global__ __launch_bounds__(256) void proj_out16(
    const float* __restrict__ bo, float* __restrict__ out)
{
    extern __shared__ uint32_t sm[];
    const int m0 = blockIdx.x * 128, e0 = blockIdx.y * 128;
    const int tid = threadIdx.x, wid = tid >> 5, lane = tid & 31;
    const int g = lane >> 2, tg = lane & 3;
    const int m_w0 = (wid >> 1) * 32, n_w0 = (wid & 1) * 64;

    float acc[2][8][4];
    #pragma unroll
    for (int mi = 0; mi < 2; ++mi)
        #pragma unroll
        for (int nj = 0; nj < 8; ++nj)
            #pragma unroll
            for (int q = 0; q < 4; ++q) acc[mi][nj][q] = 0.f;

    gemm_body16(g_ah + (size_t)m0 * D_,
                g_wh + (size_t)3 * D_ * D_ + (size_t)e0 * D_, sm, acc,
                m_w0, n_w0, tid, g, tg);

    #pragma unroll
    for (int mi = 0; mi < 2; ++mi) {
        #pragma unroll
        for (int hf = 0; hf < 2; ++hf) {
            const int m = m0 + m_w0 + mi * 16 + g + 8 * hf;
            #pragma unroll
            for (int nj = 0; nj < 8; ++nj) {
                const int e = e0 + n_w0 + nj * 8 + 2 * tg;
                float2 v;
                v.x = acc[mi][nj][2 * hf + 0] + bo[e];
                v.y = acc[mi][nj][2 * hf + 1] + bo[e + 1];
                *reinterpret_cast<float2*>(out + (size_t)m * D_ + e) = v;
            }
        }
    }
}

// ---------------------------------------------------------------------------
// Flash attention, f16 tensor cores. CTA: 256 thr / 8 warps, 128 queries
// (warp w owns rows w*16..+16). Loops 64-key tiles; online softmax in
// accumulator registers; P->A fragment via register f16x2 pack; V tile has a
// ones-row (d=64) so PV MMA accumulates the softmax denominator for free.
// ---------------------------------------------------------------------------
__device__ __forceinline__ void flash_issue(uint32_t* Ksb, uint32_t* Vtb,
                                            int bh, int kt, int tid)
{
    const char* kbase = (const char*)(g_kh + ((size_t)bh * S_ + kt * 64) * DK_);
    const char* vbase = (const char*)(g_vt + (size_t)bh * DK_ * S_ + kt * 64);
    #pragma unroll
    for (int t = 0; t < 4; ++t) {
        const int idx = tid + (t << 8);           // 0..1023
        if (idx < 512) {
            const int row = idx >> 3, ch = idx & 7;
            CP16(smem_u32(Ksb + row * PITCH + ch * 4), kbase + row * 128 + ch * 16);
        } else {
            const int i2 = idx - 512;
            const int row = i2 >> 3, ch = i2 & 7;
            CP16(smem_u32(Vtb + row * PITCH + ch * 4),
                 vbase + (size_t)row * (S_ * 2) + ch * 16);
        }
    }
    CP_COMMIT();
}

__global__ __launch_bounds__(256) void flash16()
{
    __shared__ uint32_t Ks[2][64 * PITCH];   // K tile: [key][d-pairs]
    __shared__ uint32_t Vt[2][72 * PITCH];   // V tile: [d][key-pairs], rows 64..71 static

    const int tid = threadIdx.x, w = tid >> 5, lane = tid & 31;
    const int g = lane >> 2, tg = lane & 3;
    const int bh = blockIdx.y, q0 = blockIdx.x * 128;

    // Q fragments (register-resident for all key tiles). Scale+log2e pre-folded.
    uint32_t aq[4][4];
    {
        const uint32_t* qp = (const uint32_t*)(g_qh + ((size_t)bh * S_ + q0 + w * 16) * DK_);
        #pragma unroll
        for (int s = 0; s < 4; ++s) {
            aq[s][0] = qp[g * 32 + 8 * s + tg];
            aq[s][1] = qp[(g + 8) * 32 + 8 * s + tg];
            aq[s][2] = qp[g * 32 + 8 * s + tg + 4];
            aq[s][3] = qp[(g + 8) * 32 + 8 * s + tg + 4];
        }
    }

    flash_issue(Ks[0], Vt[0], bh, 0, tid);

    // Static V rows: d=64 -> ones (softmax denominator), d=65..71 -> zeros.
    for (int i = tid; i < 8 * 32; i += 256) {
        const int r = 64 + (i >> 5), c = i & 31;
        const uint32_t v = (r == 64) ? 0x3C003C00u : 0u;
        Vt[0][r * PITCH + c] = v;
        Vt[1][r * PITCH + c] = v;
    }

    float oa[9][4];
    #pragma unroll
    for (int dj = 0; dj < 9; ++dj)
        #pragma unroll
        for (int q = 0; q < 4; ++q) oa[dj][q] = 0.f;
    float m0v = -1e30f, m1v = -1e30f;

    for (int kt = 0; kt < S_ / 64; ++kt) {
        if (kt + 1 < S_ / 64) {
            flash_issue(Ks[(kt + 1) & 1], Vt[(kt + 1) & 1], bh, kt + 1, tid);
            CP_WAIT(1);
        } else {
            CP_WAIT(0);
        }
        __syncthreads();
        const uint32_t* Kb = Ks[kt & 1];
        const uint32_t* Vb = Vt[kt & 1];

        // Scores (log2 domain): sa[nj] covers keys nj*8..+7, rows {g, g+8}.
        float sa[8][4];
        #pragma unroll
        for (int nj = 0; nj < 8; ++nj)
            #pragma unroll
            for (int q = 0; q < 4; ++q) sa[nj][q] = 0.f;

        #pragma unroll
        for (int s = 0; s < 4; ++s)
            #pragma unroll
            for (int nj = 0; nj < 8; ++nj) {
                const uint32_t* br = Kb + (nj * 8 + g) * PITCH;
                MMA_F16(sa[nj], aq[s], br[8 * s + tg], br[8 * s + tg + 4]);
            }

        // Online softmax (base-2).
        float mx0 = -1e30f, mx1 = -1e30f;
        #pragma unroll
        for (int nj = 0; nj < 8; ++nj) {
            mx0 = fmaxf(mx0, fmaxf(sa[nj][0], sa[nj][1]));
            mx1 = fmaxf(mx1, fmaxf(sa[nj][2], sa[nj][3]));
        }
        mx0 = fmaxf(mx0, __shfl_xor_sync(0xffffffffu, mx0, 1));
        mx0 = fmaxf(mx0, __shfl_xor_sync(0xffffffffu, mx0, 2));
        mx1 = fmaxf(mx1, __shfl_xor_sync(0xffffffffu, mx1, 1));
        mx1 = fmaxf(mx1, __shfl_xor_sync(0xffffffffu, mx1, 2));

        const float mn0 = fmaxf(m0v, mx0), mn1 = fmaxf(m1v, mx1);
        const float al0 = exp2a(m0v - mn0), al1 = exp2a(m1v - mn1);
        m0v = mn0; m1v = mn1;

        #pragma unroll
        for (int dj = 0; dj < 9; ++dj) {
            oa[dj][0] *= al0; oa[dj][1] *= al0;
            oa[dj][2] *= al1; oa[dj][3] *= al1;
        }
        #pragma unroll
        for (int nj = 0; nj < 8; ++nj) {
            sa[nj][0] = exp2a(sa[nj][0] - mn0);
            sa[nj][1] = exp2a(sa[nj][1] - mn0);
            sa[nj][2] = exp2a(sa[nj][2] - mn1);
            sa[nj][3] = exp2a(sa[nj][3] - mn1);
        }

        // P accumulator -> A fragments (pure register pack).
        uint32_t pk[4][4];
        #pragma unroll
        for (int s = 0; s < 4; ++s) {
            pk[s][0] = packh2(sa[2 * s][1],     sa[2 * s][0]);
            pk[s][1] = packh2(sa[2 * s][3],     sa[2 * s][2]);
            pk[s][2] = packh2(sa[2 * s + 1][1], sa[2 * s + 1][0]);
            pk[s][3] = packh2(sa[2 * s + 1][3], sa[2 * s + 1][2]);
        }

        // O += P @ V  (dj=8 accumulates the ones-column = row sums l)
        #pragma unroll
        for (int s = 0; s < 4; ++s)
            #pragma unroll
            for (int dj = 0; dj < 9; ++dj) {
                const uint32_t* br = Vb + (dj * 8 + g) * PITCH;
                MMA_F16(oa[dj], pk[s], br[8 * s + tg], br[8 * s + tg + 4]);
            }
        __syncthreads();
    }

    // Normalize by l (col 64, held by tg==0) and store f16 attn.
    float l0 = oa[8][0], l1 = oa[8][2];
    l0 = __shfl_sync(0xffffffffu, l0, lane & 28);
    l1 = __shfl_sync(0xffffffffu, l1, lane & 28);
    const float inv0 = 1.f / l0, inv1 = 1.f / l1;

    const int b = bh >> 4, h = bh & (H_ - 1);
    const int r0 = q0 + w * 16 + g, r1 = r0 + 8;
    uint32_t* out0 = (uint32_t*)(g_ah + ((size_t)b * S_ + r0) * D_ + h * DK_);
    uint32_t* out1 = (uint32_t*)(g_ah + ((size_t)b * S_ + r1) * D_ + h * DK_);
    #pragma unroll
    for (int dj = 0; dj < 8; ++dj) {
        out0[dj * 4 + tg] = packh2(oa[dj][1] * inv0, oa[dj][0] * inv0);
        out1[dj * 4 + tg] = packh2(oa[dj][3] * inv1, oa[dj][2] * inv1);
    }
}

// ---------------------------------------------------------------------------
// Launch
// ---------------------------------------------------------------------------
extern "C" void kernel_launch(void* const* d_in, const int* in_sizes, int n_in,
                              void* d_out, int out_size)
{
    const float* x  = (const float*)d_in[0];
    const float* wq = (const float*)d_in[1];
    const float* bq = (const float*)d_in[2];
    const float* wk = (const float*)d_in[3];
    const float* bk = (const float*)d_in[4];
    const float* wv = (const float*)d_in[5];
    const float* bv = (const float*)d_in[6];
    const float* wo = (const float*)d_in[7];
    const float* bo = (const float*)d_in[8];
    float* out = (float*)d_out;

    cudaFuncSetAttribute(proj_qkv16,
                         cudaFuncAttributeMaxDynamicSharedMemorySize, GEMM_SMEM);
    cudaFuncSetAttribute(proj_out16,
                         cudaFuncAttributeMaxDynamicSharedMemorySize, GEMM_SMEM);

    prep16<<<dim3((M_ * D_) / 1024, 5), 256>>>(x, wq, wk, wv, wo);
    proj_qkv16<<<dim3(M_ / 128, D_ / 128, 3), 256, GEMM_SMEM>>>(bq, bk, bv);
    flash16<<<dim3(S_ / 128, B_ * H_), 256>>>();
    proj_out16<<<dim3(M_ / 128, D_ / 128), 256, GEMM_SMEM>>>(bo, out);
}

// round 5
// speedup vs baseline: 6.8297x; 1.0137x over previous
#include <cuda_runtime.h>
#include <cuda_fp16.h>
#include <math.h>
#include <stdint.h>

// Problem dimensions (fixed by the reference).
#define B_  2
#define S_  2048
#define D_  1024
#define H_  16
#define DK_ 64
#define M_  (B_ * S_)

// Scratch (device globals: allowed; runtime allocation is not).
static __device__ __half g_xh[(size_t)M_ * D_];              // f16(x)
static __device__ __half g_wh[(size_t)4 * D_ * D_];          // f16(wq,wk,wv,wo)
static __device__ __half g_qh[(size_t)B_ * H_ * S_ * DK_];   // q * 0.125*log2e (B,H,S,DK)
static __device__ __half g_kh[(size_t)B_ * H_ * S_ * DK_];   // k (B,H,S,DK)
static __device__ __half g_vt[(size_t)B_ * H_ * DK_ * S_];   // v TRANSPOSED (B,H,DK,S)
static __device__ __half g_ah[(size_t)M_ * D_];              // attn out f16 (B,S,D)

// ---------------------------------------------------------------------------
// Helpers
// ---------------------------------------------------------------------------
__device__ __forceinline__ uint32_t smem_u32(const void* p) {
    uint32_t a;
    asm("{ .reg .u64 t; cvta.to.shared.u64 t, %1; cvt.u32.u64 %0, t; }" : "=r"(a) : "l"(p));
    return a;
}

__device__ __forceinline__ float exp2a(float x) {
    float y;
    asm("ex2.approx.f32 %0, %1;" : "=f"(y) : "f"(x));
    return y;
}

// packs {lo, hi} into f16x2 (first asm source = high half)
__device__ __forceinline__ uint32_t packh2(float hi, float lo) {
    uint32_t r;
    asm("cvt.rn.f16x2.f32 %0, %1, %2;" : "=r"(r) : "f"(hi), "f"(lo));
    return r;
}

#define CP16(dst, src) \
    asm volatile("cp.async.cg.shared.global [%0], [%1], 16;" :: "r"(dst), "l"(src) : "memory")
#define CP_COMMIT()  asm volatile("cp.async.commit_group;" ::: "memory")
#define CP_WAIT(n)   asm volatile("cp.async.wait_group %0;" :: "n"(n) : "memory")

// m16n8k16 f16 MMA, f32 accumulate: D += A(16x16 row) * B(16x8 col)
#define MMA_F16(d, a, b0, b1) \
    asm volatile( \
        "mma.sync.aligned.m16n8k16.row.col.f32.f16.f16.f32 " \
        "{%0,%1,%2,%3}, {%4,%5,%6,%7}, {%8,%9}, {%0,%1,%2,%3};" \
        : "+f"((d)[0]), "+f"((d)[1]), "+f"((d)[2]), "+f"((d)[3]) \
        : "r"((a)[0]), "r"((a)[1]), "r"((a)[2]), "r"((a)[3]), \
          "r"(b0), "r"(b1))

#define LDSM4(r, addr) \
    asm volatile("ldmatrix.sync.aligned.m8n8.x4.shared.b16 {%0,%1,%2,%3}, [%4];" \
        : "=r"((r)[0]), "=r"((r)[1]), "=r"((r)[2]), "=r"((r)[3]) : "r"(addr))
#define LDSM2(r0, r1, addr) \
    asm volatile("ldmatrix.sync.aligned.m8n8.x2.shared.b16 {%0,%1}, [%2];" \
        : "=r"(r0), "=r"(r1) : "r"(addr))

// ---------------------------------------------------------------------------
// f16 GEMM: C[128x128] = A[128xD] * W[128xD]^T (f16 in, f32 acc)
// 256 threads / 8 warps; warp tile 32m x 64n. Smem rows of 32 u32 (64 f16),
// pitch 36 u32 -> ldmatrix row stride 144B = 4 banks; each 8-row LDSM phase
// covers all 32 banks exactly once (conflict-free).
// 3-stage cp.async pipeline, ONE __syncthreads per 64-f16 K-chunk.
// ---------------------------------------------------------------------------
#define PITCH 36
#define TILE_U (128 * PITCH)               // u32 per 128x64 tile
#define STAGE_U (2 * TILE_U)               // A + W per stage
#define GEMM_SMEM (3 * STAGE_U * 4)        // 110592 bytes

__device__ __forceinline__ void issue_chunk16(const __half* __restrict__ Ag,
                                              const __half* __restrict__ Wg,
                                              uint32_t sbase, int stage, int c, int tid)
{
    const uint32_t As = sbase + stage * (STAGE_U * 4);
    const uint32_t Ws = As + TILE_U * 4;
    const char* Ab = (const char*)Ag + c * 128;   // 64 f16 = 128 B per chunk
    const char* Wb = (const char*)Wg + c * 128;
    #pragma unroll
    for (int t = 0; t < 8; ++t) {
        const int idx = tid + (t << 8);           // 0..2047
        const int sel = idx >> 10;                // 0 = A, 1 = W
        const int i2  = idx & 1023;
        const int row = i2 >> 3, ch = i2 & 7;
        const uint32_t dst = (sel ? Ws : As) + (uint32_t)(row * PITCH + ch * 4) * 4u;
        const char* src = (sel ? Wb : Ab) + (size_t)row * (D_ * 2) + ch * 16;
        CP16(dst, src);
    }
    CP_COMMIT();
}

__device__ __forceinline__ void compute_chunk16(uint32_t aAddr, uint32_t wAddr,
                                                float (&acc)[2][8][4])
{
    #pragma unroll
    for (int s = 0; s < 4; ++s) {
        uint32_t a0[4], a1[4];
        LDSM4(a0, aAddr + s * 32);
        LDSM4(a1, aAddr + 16 * PITCH * 4 + s * 32);
        #pragma unroll
        for (int p = 0; p < 4; ++p) {
            uint32_t b[4];
            LDSM4(b, wAddr + p * 16 * PITCH * 4 + s * 32);
            MMA_F16(acc[0][2 * p],     a0, b[0], b[2]);
            MMA_F16(acc[0][2 * p + 1], a0, b[1], b[3]);
            MMA_F16(acc[1][2 * p],     a1, b[0], b[2]);
            MMA_F16(acc[1][2 * p + 1], a1, b[1], b[3]);
        }
    }
}

__device__ __forceinline__ void gemm_body16(const __half* __restrict__ Ag,
                                            const __half* __restrict__ Wg,
                                            uint32_t* sm, float (&acc)[2][8][4],
                                            int m_w0, int n_w0, int tid)
{
    const int lane = tid & 31;
    const int lr = lane & 15, lh = lane >> 4;
    const uint32_t sbase = smem_u32(sm);
    const uint32_t aFrag = sbase + (uint32_t)((m_w0 + lr) * PITCH + 4 * lh) * 4u;
    const uint32_t wFrag = sbase + (uint32_t)(TILE_U + (n_w0 + lr) * PITCH + 4 * lh) * 4u;

    issue_chunk16(Ag, Wg, sbase, 0, 0, tid);
    issue_chunk16(Ag, Wg, sbase, 1, 1, tid);

    #pragma unroll 1
    for (int c = 0; c < 16; ++c) {
        if (c < 15) { CP_WAIT(1); } else { CP_WAIT(0); }
        __syncthreads();
        if (c + 2 < 16)
            issue_chunk16(Ag, Wg, sbase, (c + 2) % 3, c + 2, tid);
        const uint32_t so = (uint32_t)((c % 3) * STAGE_U * 4);
        compute_chunk16(aFrag + so, wFrag + so, acc);
    }
}

// ---------------------------------------------------------------------------
// Prep: convert x + weights to f16.
// ---------------------------------------------------------------------------
__global__ __launch_bounds__(256) void prep16(
    const float* __restrict__ x,
    const float* __restrict__ wq, const float* __restrict__ wk,
    const float* __restrict__ wv, const float* __restrict__ wo)
{
    const int r = blockIdx.y;
    const float* src = (r == 0) ? x : (r == 1) ? wq : (r == 2) ? wk : (r == 3) ? wv : wo;
    __half* dst = (r == 0) ? g_xh : g_wh + (size_t)(r - 1) * D_ * D_;
    const size_t n = (r == 0) ? (size_t)M_ * D_ : (size_t)D_ * D_;
    const size_t i = ((size_t)blockIdx.x * 256 + threadIdx.x) * 4;
    if (i < n) {
        const float4 v = *reinterpret_cast<const float4*>(src + i);
        uint2 o;
        o.x = packh2(v.y, v.x);
        o.y = packh2(v.w, v.z);
        *reinterpret_cast<uint2*>(dst + i) = o;
    }
}

// ---------------------------------------------------------------------------
// QKV projection: grid (32, 8, 3). Q gets 0.125*log2e folded in; V stored
// transposed (B,H,DK,S) for the flash B-operand.
// ---------------------------------------------------------------------------
__global__ __launch_bounds__(256) void proj_qkv16(
    const float* __restrict__ bq, const float* __restrict__ bk,
    const float* __restrict__ bv)
{
    extern __shared__ uint32_t sm[];
    const int z = blockIdx.z;
    const float* bias = (z == 0) ? bq : (z == 1) ? bk : bv;
    const __half* W = g_wh + (size_t)z * D_ * D_;

    const int m0 = blockIdx.x * 128, e0 = blockIdx.y * 128;
    const int tid = threadIdx.x, wid = tid >> 5, lane = tid & 31;
    const int g = lane >> 2, tg = lane & 3;
    const int m_w0 = (wid >> 1) * 32, n_w0 = (wid & 1) * 64;

    float acc[2][8][4];
    #pragma unroll
    for (int mi = 0; mi < 2; ++mi)
        #pragma unroll
        for (int nj = 0; nj < 8; ++nj)
            #pragma unroll
            for (int q = 0; q < 4; ++q) acc[mi][nj][q] = 0.f;

    gemm_body16(g_xh + (size_t)m0 * D_, W + (size_t)e0 * D_, sm, acc, m_w0, n_w0, tid);

    #pragma unroll
    for (int mi = 0; mi < 2; ++mi) {
        #pragma unroll
        for (int hf = 0; hf < 2; ++hf) {
            const int m = m0 + m_w0 + mi * 16 + g + 8 * hf;
            const int b = m >> 11, s = m & (S_ - 1);
            #pragma unroll
            for (int nj = 0; nj < 8; ++nj) {
                const int e = e0 + n_w0 + nj * 8 + 2 * tg;
                float v0 = acc[mi][nj][2 * hf + 0] + bias[e];
                float v1 = acc[mi][nj][2 * hf + 1] + bias[e + 1];
                const int hh = e >> 6, dk = e & (DK_ - 1);
                const size_t bh = (size_t)(b * H_ + hh);
                if (z == 0) {
                    v0 *= 0.1803368801f;     // 0.125 * log2(e)
                    v1 *= 0.1803368801f;
                    ((uint32_t*)g_qh)[(bh * S_ + s) * 32 + (dk >> 1)] = packh2(v1, v0);
                } else if (z == 1) {
                    ((uint32_t*)g_kh)[(bh * S_ + s) * 32 + (dk >> 1)] = packh2(v1, v0);
                } else {
                    g_vt[(bh * DK_ + dk) * S_ + s]     = __float2half_rn(v0);
                    g_vt[(bh * DK_ + dk + 1) * S_ + s] = __float2half_rn(v1);
                }
            }
        }
    }
}

// ---------------------------------------------------------------------------
// Output projection: grid (32, 8), reads f16 attn, writes f32 out.
// ---------------------------------------------------------------------------
__global__ __launch_bounds__(256) void proj_out16(
    const float* __restrict__ bo, float* __restrict__ out)
{
    extern __shared__ uint32_t sm[];
    const int m0 = blockIdx.x * 128, e0 = blockIdx.y * 128;
    const int tid = threadIdx.x, wid = tid >> 5, lane = tid & 31;
    const int g = lane >> 2, tg = lane & 3;
    const int m_w0 = (wid >> 1) * 32, n_w0 = (wid & 1) * 64;

    float acc[2][8][4];
    #pragma unroll
    for (int mi = 0; mi < 2; ++mi)
        #pragma unroll
        for (int nj = 0; nj < 8; ++nj)
            #pragma unroll
            for (int q = 0; q < 4; ++q) acc[mi][nj][q] = 0.f;

    gemm_body16(g_ah + (size_t)m0 * D_,
                g_wh + (size_t)3 * D_ * D_ + (size_t)e0 * D_, sm, acc, m_w0, n_w0, tid);

    #pragma unroll
    for (int mi = 0; mi < 2; ++mi) {
        #pragma unroll
        for (int hf = 0; hf < 2; ++hf) {
            const int m = m0 + m_w0 + mi * 16 + g + 8 * hf;
            #pragma unroll
            for (int nj = 0; nj < 8; ++nj) {
                const int e = e0 + n_w0 + nj * 8 + 2 * tg;
                float2 v;
                v.x = acc[mi][nj][2 * hf + 0] + bo[e];
                v.y = acc[mi][nj][2 * hf + 1] + bo[e + 1];
                *reinterpret_cast<float2*>(out + (size_t)m * D_ + e) = v;
            }
        }
    }
}

// ---------------------------------------------------------------------------
// Flash attention, f16 tensor cores + ldmatrix. CTA: 256 thr / 8 warps,
// 128 queries (warp w owns rows w*16..+16). 3-stage cp.async over 64-key
// tiles, ONE sync per tile. V tile carries a ones-row (d=64) so the PV MMA
// accumulates the softmax denominator for free.
// Smem layout (dynamic): K stages [3][64*PITCH] u32, then V stages [3][72*PITCH].
// ---------------------------------------------------------------------------
#define KTILE_U (64 * PITCH)
#define VTILE_U (72 * PITCH)
#define FLASH_SMEM ((3 * KTILE_U + 3 * VTILE_U) * 4)   // 58752 bytes

__device__ __forceinline__ void flash_issue(uint32_t sbase, int stage,
                                            int bh, int kt, int tid)
{
    const uint32_t Kb = sbase + stage * (KTILE_U * 4);
    const uint32_t Vb = sbase + (3 * KTILE_U + stage * VTILE_U) * 4;
    const char* kbase = (const char*)(g_kh + ((size_t)bh * S_ + kt * 64) * DK_);
    const char* vbase = (const char*)(g_vt + (size_t)bh * DK_ * S_ + kt * 64);
    #pragma unroll
    for (int t = 0; t < 4; ++t) {
        const int idx = tid + (t << 8);           // 0..1023
        if (idx < 512) {
            const int row = idx >> 3, ch = idx & 7;
            CP16(Kb + (uint32_t)(row * PITCH + ch * 4) * 4u, kbase + row * 128 + ch * 16);
        } else {
            const int i2 = idx - 512;
            const int row = i2 >> 3, ch = i2 & 7;
            CP16(Vb + (uint32_t)(row * PITCH + ch * 4) * 4u,
                 vbase + (size_t)row * (S_ * 2) + ch * 16);
        }
    }
    CP_COMMIT();
}

__global__ __launch_bounds__(256) void flash16()
{
    extern __shared__ uint32_t smf[];
    const uint32_t sbase = smem_u32(smf);

    const int tid = threadIdx.x, w = tid >> 5, lane = tid & 31;
    const int g = lane >> 2, tg = lane & 3;
    const int lr = lane & 15, lh = lane >> 4;
    const int bh = blockIdx.y, q0 = blockIdx.x * 128;

    // Q fragments (register-resident for all key tiles). Scale+log2e pre-folded.
    uint32_t aq[4][4];
    {
        const uint32_t* qp = (const uint32_t*)(g_qh + ((size_t)bh * S_ + q0 + w * 16) * DK_);
        #pragma unroll
        for (int s = 0; s < 4; ++s) {
            aq[s][0] = qp[g * 32 + 8 * s + tg];
            aq[s][1] = qp[(g + 8) * 32 + 8 * s + tg];
            aq[s][2] = qp[g * 32 + 8 * s + tg + 4];
            aq[s][3] = qp[(g + 8) * 32 + 8 * s + tg + 4];
        }
    }

    flash_issue(sbase, 0, bh, 0, tid);
    flash_issue(sbase, 1, bh, 1, tid);

    // Static V rows (all 3 stages): d=64 -> ones (denominator), 65..71 -> zeros.
    for (int i = tid; i < 3 * 8 * 32; i += 256) {
        const int st = i >> 8, r = 64 + ((i >> 5) & 7), c = i & 31;
        smf[3 * KTILE_U + st * VTILE_U + r * PITCH + c] =
            (r == 64) ? 0x3C003C00u : 0u;
    }

    // Per-lane fragment addresses (stage 0; add stage offsets in-loop).
    const uint32_t kFrag  = sbase + (uint32_t)(lr * PITCH + 4 * lh) * 4u;
    const uint32_t vFrag  = sbase + (uint32_t)(3 * KTILE_U + lr * PITCH + 4 * lh) * 4u;
    const uint32_t vFrag8 = sbase + (uint32_t)(3 * KTILE_U +
                              (64 + (lane & 7)) * PITCH + 4 * ((lane >> 3) & 1)) * 4u;

    float oa[9][4];
    #pragma unroll
    for (int dj = 0; dj < 9; ++dj)
        #pragma unroll
        for (int q = 0; q < 4; ++q) oa[dj][q] = 0.f;
    float m0v = -1e30f, m1v = -1e30f;

    #pragma unroll 1
    for (int kt = 0; kt < S_ / 64; ++kt) {
        if (kt < S_ / 64 - 1) { CP_WAIT(1); } else { CP_WAIT(0); }
        __syncthreads();
        if (kt + 2 < S_ / 64)
            flash_issue(sbase, (kt + 2) % 3, bh, kt + 2, tid);

        const int st = kt % 3;
        const uint32_t kA = kFrag + (uint32_t)(st * KTILE_U * 4);
        const uint32_t vA = vFrag + (uint32_t)(st * VTILE_U * 4);
        const uint32_t vA8 = vFrag8 + (uint32_t)(st * VTILE_U * 4);

        // Scores (log2 domain): sa[nj] covers keys nj*8..+7, rows {g, g+8}.
        float sa[8][4];
        #pragma unroll
        for (int nj = 0; nj < 8; ++nj)
            #pragma unroll
            for (int q = 0; q < 4; ++q) sa[nj][q] = 0.f;

        #pragma unroll
        for (int s = 0; s < 4; ++s)
            #pragma unroll
            for (int p = 0; p < 4; ++p) {
                uint32_t b[4];
                LDSM4(b, kA + p * 16 * PITCH * 4 + s * 32);
                MMA_F16(sa[2 * p],     aq[s], b[0], b[2]);
                MMA_F16(sa[2 * p + 1], aq[s], b[1], b[3]);
            }

        // Online softmax (base-2).
        float mx0 = -1e30f, mx1 = -1e30f;
        #pragma unroll
        for (int nj = 0; nj < 8; ++nj) {
            mx0 = fmaxf(mx0, fmaxf(sa[nj][0], sa[nj][1]));
            mx1 = fmaxf(mx1, fmaxf(sa[nj][2], sa[nj][3]));
        }
        mx0 = fmaxf(mx0, __shfl_xor_sync(0xffffffffu, mx0, 1));
        mx0 = fmaxf(mx0, __shfl_xor_sync(0xffffffffu, mx0, 2));
        mx1 = fmaxf(mx1, __shfl_xor_sync(0xffffffffu, mx1, 1));
        mx1 = fmaxf(mx1, __shfl_xor_sync(0xffffffffu, mx1, 2));

        const float mn0 = fmaxf(m0v, mx0), mn1 = fmaxf(m1v, mx1);
        const float al0 = exp2a(m0v - mn0), al1 = exp2a(m1v - mn1);
        m0v = mn0; m1v = mn1;

        #pragma unroll
        for (int dj = 0; dj < 9; ++dj) {
            oa[dj][0] *= al0; oa[dj][1] *= al0;
            oa[dj][2] *= al1; oa[dj][3] *= al1;
        }
        #pragma unroll
        for (int nj = 0; nj < 8; ++nj) {
            sa[nj][0] = exp2a(sa[nj][0] - mn0);
            sa[nj][1] = exp2a(sa[nj][1] - mn0);
            sa[nj][2] = exp2a(sa[nj][2] - mn1);
            sa[nj][3] = exp2a(sa[nj][3] - mn1);
        }

        // P accumulator -> A fragments (pure register pack).
        uint32_t pk[4][4];
        #pragma unroll
        for (int s = 0; s < 4; ++s) {
            pk[s][0] = packh2(sa[2 * s][1],     sa[2 * s][0]);
            pk[s][1] = packh2(sa[2 * s][3],     sa[2 * s][2]);
            pk[s][2] = packh2(sa[2 * s + 1][1], sa[2 * s + 1][0]);
            pk[s][3] = packh2(sa[2 * s + 1][3], sa[2 * s + 1][2]);
        }

        // O += P @ V  (oa[8] accumulates the ones-column = row sums l)
        #pragma unroll
        for (int s = 0; s < 4; ++s) {
            #pragma unroll
            for (int p = 0; p < 4; ++p) {
                uint32_t b[4];
                LDSM4(b, vA + p * 16 * PITCH * 4 + s * 32);
                MMA_F16(oa[2 * p],     pk[s], b[0], b[2]);
                MMA_F16(oa[2 * p + 1], pk[s], b[1], b[3]);
            }
            uint32_t b0, b1;
            LDSM2(b0, b1, vA8 + s * 32);
            MMA_F16(oa[8], pk[s], b0, b1);
        }
    }

    // Normalize by l (col 64, held by tg==0) and store f16 attn.
    float l0 = oa[8][0], l1 = oa[8][2];
    l0 = __shfl_sync(0xffffffffu, l0, lane & 28);
    l1 = __shfl_sync(0xffffffffu, l1, lane & 28);
    const float inv0 = 1.f / l0, inv1 = 1.f / l1;

    const int b = bh >> 4, h = bh & (H_ - 1);
    const int r0 = q0 + w * 16 + g, r1 = r0 + 8;
    uint32_t* out0 = (uint32_t*)(g_ah + ((size_t)b * S_ + r0) * D_ + h * DK_);
    uint32_t* out1 = (uint32_t*)(g_ah + ((size_t)b * S_ + r1) * D_ + h * DK_);
    #pragma unroll
    for (int dj = 0; dj < 8; ++dj) {
        out0[dj * 4 + tg] = packh2(oa[dj][1] * inv0, oa[dj][0] * inv0);
        out1[dj * 4 + tg] = packh2(oa[dj][3] * inv1, oa[dj][2] * inv1);
    }
}

// ---------------------------------------------------------------------------
// Launch
// ---------------------------------------------------------------------------
extern "C" void kernel_launch(void* const* d_in, const int* in_sizes, int n_in,
                              void* d_out, int out_size)
{
    const float* x  = (const float*)d_in[0];
    const float* wq = (const float*)d_in[1];
    const float* bq = (const float*)d_in[2];
    const float* wk = (const float*)d_in[3];
    const float* bk = (const float*)d_in[4];
    const float* wv = (const float*)d_in[5];
    const float* bv = (const float*)d_in[6];
    const float* wo = (const float*)d_in[7];
    const float* bo = (const float*)d_in[8];
    float* out = (float*)d_out;

    cudaFuncSetAttribute(proj_qkv16,
                         cudaFuncAttributeMaxDynamicSharedMemorySize, GEMM_SMEM);
    cudaFuncSetAttribute(proj_out16,
                         cudaFuncAttributeMaxDynamicSharedMemorySize, GEMM_SMEM);
    cudaFuncSetAttribute(flash16,
                         cudaFuncAttributeMaxDynamicSharedMemorySize, FLASH_SMEM);

    prep16<<<dim3((M_ * D_) / 1024, 5), 256>>>(x, wq, wk, wv, wo);
    proj_qkv16<<<dim3(M_ / 128, D_ / 128, 3), 256, GEMM_SMEM>>>(bq, bk, bv);
    flash16<<<dim3(S_ / 128, B_ * H_), 256, FLASH_SMEM>>>();
    proj_out16<<<dim3(M_ / 128, D_ / 128), 256, GEMM_SMEM>>>(bo, out);
}